// round 12
// baseline (speedup 1.0000x reference)
#include <cuda_runtime.h>
#include <cuda_bf16.h>
#include <mma.h>
#include <cstdint>

using namespace nvcuda;

#define NN 30000
#define EE 600000
#define HH 128
#define LL 4
#define GG 64
#define TMR 64       // rows per tile (2 CTAs/SM)
#define LDA 136      // leading dim (elements) for bf16 planes and float stage
#define WROWS 769    // per-layer pre-split weight rows: 257 + 128 + 256 + 128

// ---------------- scratch (static device globals; no allocation) ----------
__device__ __align__(256) float g_h[NN * HH];        // fp32 h (for pool)
__device__ __align__(256) __nv_bfloat16 g_hhi[NN * HH];
__device__ __align__(256) __nv_bfloat16 g_hmid[NN * HH];
__device__ __align__(256) float g_aggr[NN * HH];
__device__ __align__(256) float g_msg[(size_t)EE * HH];   // per-edge messages (307MB)
__device__ __align__(256) float g_dist[EE];
__device__ __align__(256) float g_pool[GG * HH];
__device__ __align__(256) __nv_bfloat16 g_whi[LL * WROWS * HH];
__device__ __align__(256) __nv_bfloat16 g_wmid[LL * WROWS * HH];
__device__ int g_cnt[NN];
__device__ int g_off[NN + 1];
__device__ int g_cursor[NN];
__device__ int g_perm[EE];
__device__ int g_is64;

// ---------------- helpers ----------------
__device__ __forceinline__ int ld_idx(const void* p, long long i, int is64) {
    if (is64) return (int)((const long long*)p)[i];
    return ((const int*)p)[i];
}
__device__ __forceinline__ float silu_f(float v) {
    return v / (1.0f + __expf(-v));
}
__device__ __forceinline__ void split_bf16(float x, __nv_bfloat16& h, __nv_bfloat16& m) {
    h = __float2bfloat16_rn(x);
    float r = x - __bfloat162float(h);
    m = __float2bfloat16_rn(r);
}

// ---------------- auxiliary kernels ----------------
__global__ void detect_kernel(const int* w) {
    __shared__ int nz;
    if (threadIdx.x == 0) nz = 0;
    __syncthreads();
    int f = 0;
    for (int i = threadIdx.x * 2 + 1; i < 4096; i += 2 * 256)
        if (w[i] != 0) f = 1;
    if (f) atomicOr(&nz, 1);
    __syncthreads();
    if (threadIdx.x == 0) g_is64 = (nz == 0) ? 1 : 0;
}

__global__ void prep_w_kernel(const float* __restrict__ msg_w1,
                              const float* __restrict__ msg_w2,
                              const float* __restrict__ node_w1,
                              const float* __restrict__ node_w2) {
    int id = blockIdx.x * blockDim.x + threadIdx.x;
    if (id >= LL * WROWS * HH) return;
    int l = id / (WROWS * HH);
    int rem = id - l * (WROWS * HH);
    int row = rem >> 7, n = rem & 127;
    float v;
    if (row < 257)      v = msg_w1[((size_t)l * 257 + row) * HH + n];
    else if (row < 385) v = msg_w2[((size_t)l * 128 + (row - 257)) * HH + n];
    else if (row < 641) v = node_w1[((size_t)l * 256 + (row - 385)) * HH + n];
    else                v = node_w2[((size_t)l * 128 + (row - 641)) * HH + n];
    __nv_bfloat16 h, m;
    split_bf16(v, h, m);
    g_whi[id] = h;
    g_wmid[id] = m;
}

__global__ void embed_kernel(const float* __restrict__ x,
                             const float* __restrict__ w,
                             const float* __restrict__ b) {
    int idx = blockIdx.x * blockDim.x + threadIdx.x;
    if (idx >= NN * HH) return;
    int n = idx >> 7, k = idx & 127;
    float v = x[n] * w[k] + b[k];
    g_h[idx] = v;
    __nv_bfloat16 h, m;
    split_bf16(v, h, m);
    g_hhi[idx] = h;
    g_hmid[idx] = m;
}

__global__ void dist_kernel(const float* __restrict__ pos, const void* ei) {
    int e = blockIdx.x * blockDim.x + threadIdx.x;
    if (e >= EE) return;
    int is64 = g_is64;
    int r = ld_idx(ei, e, is64);
    int c = ld_idx(ei, (long long)EE + e, is64);
    float dx = pos[3 * r + 0] - pos[3 * c + 0];
    float dy = pos[3 * r + 1] - pos[3 * c + 1];
    float dz = pos[3 * r + 2] - pos[3 * c + 2];
    g_dist[e] = dx * dx + dy * dy + dz * dz;
}

// ---------------- CSR build (once per launch) ----------------
__global__ void zero_cnt_kernel() {
    int i = blockIdx.x * blockDim.x + threadIdx.x;
    if (i < NN) g_cnt[i] = 0;
}
__global__ void hist_kernel(const void* ei) {
    int e = blockIdx.x * blockDim.x + threadIdx.x;
    if (e >= EE) return;
    atomicAdd(&g_cnt[ld_idx(ei, (long long)EE + e, g_is64)], 1);
}
__global__ void scan_kernel() {
    __shared__ int ssum[1024];
    const int t = threadIdx.x;
    const int base = t * 30;   // 1024*30 = 30720 >= NN
    int s = 0;
    for (int i = 0; i < 30; i++) {
        int idx = base + i;
        if (idx < NN) s += g_cnt[idx];
    }
    ssum[t] = s;
    __syncthreads();
    for (int off = 1; off < 1024; off <<= 1) {
        int v = (t >= off) ? ssum[t - off] : 0;
        __syncthreads();
        ssum[t] += v;
        __syncthreads();
    }
    int run = (t == 0) ? 0 : ssum[t - 1];
    for (int i = 0; i < 30; i++) {
        int idx = base + i;
        if (idx < NN) {
            g_off[idx] = run;
            g_cursor[idx] = run;
            run += g_cnt[idx];
        }
    }
    if (t == 1023) g_off[NN] = run;
}
__global__ void fill_kernel(const void* ei) {
    int e = blockIdx.x * blockDim.x + threadIdx.x;
    if (e >= EE) return;
    int c = ld_idx(ei, (long long)EE + e, g_is64);
    int pos = atomicAdd(&g_cursor[c], 1);
    g_perm[pos] = e;
}

// ---------------- aggregate: warp per node, gather CSR messages ----------
__global__ __launch_bounds__(256) void aggregate_kernel() {
    const int wid = threadIdx.x >> 5, lane = threadIdx.x & 31;
    const int n = blockIdx.x * 8 + wid;
    if (n >= NN) return;
    const int start = g_off[n], end = g_off[n + 1];
    float4 a0 = make_float4(0.f, 0.f, 0.f, 0.f);
    float4 a1 = make_float4(0.f, 0.f, 0.f, 0.f);
    int i = start;
    for (; i + 1 < end; i += 2) {
        int e0 = g_perm[i], e1 = g_perm[i + 1];
        float4 v0 = *(const float4*)(g_msg + (size_t)e0 * HH + lane * 4);
        float4 v1 = *(const float4*)(g_msg + (size_t)e1 * HH + lane * 4);
        a0.x += v0.x; a0.y += v0.y; a0.z += v0.z; a0.w += v0.w;
        a1.x += v1.x; a1.y += v1.y; a1.z += v1.z; a1.w += v1.w;
    }
    if (i < end) {
        int e0 = g_perm[i];
        float4 v0 = *(const float4*)(g_msg + (size_t)e0 * HH + lane * 4);
        a0.x += v0.x; a0.y += v0.y; a0.z += v0.z; a0.w += v0.w;
    }
    a0.x += a1.x; a0.y += a1.y; a0.z += a1.z; a0.w += a1.w;
    *(float4*)(g_aggr + (size_t)n * HH + lane * 4) = a0;
}

__global__ void zero_pool_kernel() {
    int idx = blockIdx.x * blockDim.x + threadIdx.x;
    if (idx < GG * HH) g_pool[idx] = 0.0f;
}

// ---------------------------------------------------------------------------
// Fused MLP layer kernel (WMMA bf16, 2-way split, 3-term). TMR=64 -> 2 CTAs/SM.
// mode 0 = edge, 1 = node.
// SMEM: sAhi|sAmid (64x136 each) | sBhi|sBmid (128x136 each);
//       stage float[64][136] overlays sBhi; sCol/sRow at end. Total 104960 B.
// ---------------------------------------------------------------------------
#define SMEM_LAYER 104960

__global__ __launch_bounds__(256) void layer_kernel(
    int mode, int layer, const void* __restrict__ ei,
    const float* __restrict__ W1f,
    const float* __restrict__ B1, const float* __restrict__ B2) {
    extern __shared__ char smem[];
    __nv_bfloat16* sAhi  = (__nv_bfloat16*)smem;                 // 64*136
    __nv_bfloat16* sAmid = sAhi + TMR * LDA;
    __nv_bfloat16* sBhi  = sAmid + TMR * LDA;                    // 128*136
    __nv_bfloat16* sBmid = sBhi + 128 * LDA;
    float* stage = (float*)sBhi;                                 // 64*136 floats
    int* sCol = (int*)(sBmid + 128 * LDA);
    int* sRow = sCol + TMR;

    const size_t lbase = (size_t)layer * WROWS * HH;
    const __nv_bfloat16* w1hi  = g_whi  + lbase + (size_t)(mode == 0 ? 0 : 385) * HH;
    const __nv_bfloat16* w1mid = g_wmid + lbase + (size_t)(mode == 0 ? 0 : 385) * HH;
    const __nv_bfloat16* w2hi  = g_whi  + lbase + (size_t)(mode == 0 ? 257 : 641) * HH;
    const __nv_bfloat16* w2mid = g_wmid + lbase + (size_t)(mode == 0 ? 257 : 641) * HH;

    const int tid = threadIdx.x, lane = tid & 31, wid = tid >> 5;
    const int wr = wid & 1, wc = wid >> 1;        // warp tile: rows [wr*32,+32), cols [wc*32,+32)
    const int tile = blockIdx.x;
    const int is64 = g_is64;

    if (tid < TMR) {
        if (mode == 0) {
            long long e = (long long)tile * TMR + tid;
            long long ec = (e < EE) ? e : 0;
            sRow[tid] = ld_idx(ei, ec, is64);
            sCol[tid] = ld_idx(ei, (long long)EE + ec, is64);
        } else {
            int n = tile * TMR + tid;
            sCol[tid] = (n < NN) ? n : 0;
        }
    }
    __syncthreads();

    wmma::fragment<wmma::accumulator, 16, 16, 16, float> acc[2][2];
#pragma unroll
    for (int mt = 0; mt < 2; mt++)
#pragma unroll
        for (int nt = 0; nt < 2; nt++)
            wmma::fill_fragment(acc[mt][nt], 0.0f);

    // ================= GEMM1: K chunks of 128 =================
    for (int c = 0; c < 2; c++) {
        if (c) __syncthreads();

        // ---- A chunk: 4 threads/row, 32 elems each ----
        const int r = tid >> 2, q4 = tid & 3;
        if (mode == 0 || c == 0) {
            const int node = (mode == 0) ? ((c == 0) ? sCol[r] : sRow[r]) : sCol[r];
            const uint4* shi = (const uint4*)(g_hhi + (size_t)node * HH + q4 * 32);
            const uint4* smi = (const uint4*)(g_hmid + (size_t)node * HH + q4 * 32);
            uint4* dh = (uint4*)(sAhi + r * LDA + q4 * 32);
            uint4* dm = (uint4*)(sAmid + r * LDA + q4 * 32);
#pragma unroll
            for (int i = 0; i < 4; i++) { dh[i] = shi[i]; dm[i] = smi[i]; }
        } else {
            const float4* s4 = (const float4*)(g_aggr + (size_t)sCol[r] * HH + q4 * 32);
            __nv_bfloat16* dh = sAhi + r * LDA + q4 * 32;
            __nv_bfloat16* dm = sAmid + r * LDA + q4 * 32;
#pragma unroll
            for (int i = 0; i < 8; i++) {
                float4 v = s4[i];
                split_bf16(v.x, dh[i * 4 + 0], dm[i * 4 + 0]);
                split_bf16(v.y, dh[i * 4 + 1], dm[i * 4 + 1]);
                split_bf16(v.z, dh[i * 4 + 2], dm[i * 4 + 2]);
                split_bf16(v.w, dh[i * 4 + 3], dm[i * 4 + 3]);
            }
        }
        // ---- B chunk: 2 threads/row, 64 elems each ----
        {
            const int k = tid >> 1, half = tid & 1;
            const uint4* shi = (const uint4*)(w1hi + (size_t)(c * 128 + k) * HH + half * 64);
            const uint4* smi = (const uint4*)(w1mid + (size_t)(c * 128 + k) * HH + half * 64);
            uint4* dh = (uint4*)(sBhi + k * LDA + half * 64);
            uint4* dm = (uint4*)(sBmid + k * LDA + half * 64);
#pragma unroll
            for (int i = 0; i < 8; i++) { dh[i] = shi[i]; dm[i] = smi[i]; }
        }
        __syncthreads();

        for (int ks = 0; ks < 8; ks++) {
            const int k0 = ks * 16;
            wmma::fragment<wmma::matrix_b, 16, 16, 16, __nv_bfloat16, wmma::row_major> bh[2], bm[2];
#pragma unroll
            for (int nt = 0; nt < 2; nt++) {
                wmma::load_matrix_sync(bh[nt], sBhi + k0 * LDA + wc * 32 + nt * 16, LDA);
                wmma::load_matrix_sync(bm[nt], sBmid + k0 * LDA + wc * 32 + nt * 16, LDA);
            }
#pragma unroll
            for (int mt = 0; mt < 2; mt++) {
                const int r0 = wr * 32 + mt * 16;
                wmma::fragment<wmma::matrix_a, 16, 16, 16, __nv_bfloat16, wmma::row_major> ah, am;
                wmma::load_matrix_sync(ah, sAhi + r0 * LDA + k0, LDA);
                wmma::load_matrix_sync(am, sAmid + r0 * LDA + k0, LDA);
#pragma unroll
                for (int nt = 0; nt < 2; nt++) {
                    wmma::mma_sync(acc[mt][nt], ah, bh[nt], acc[mt][nt]);
                    wmma::mma_sync(acc[mt][nt], ah, bm[nt], acc[mt][nt]);
                    wmma::mma_sync(acc[mt][nt], am, bh[nt], acc[mt][nt]);
                }
            }
        }
    }
    __syncthreads();   // GEMM1 reads of B planes done; stage may be written

    // ---- store acc1 -> stage ----
#pragma unroll
    for (int mt = 0; mt < 2; mt++)
#pragma unroll
        for (int nt = 0; nt < 2; nt++)
            wmma::store_matrix_sync(stage + (wr * 32 + mt * 16) * LDA + wc * 32 + nt * 16,
                                    acc[mt][nt], LDA, wmma::mem_row_major);
    __syncthreads();

    // ---- epilogue 1: D1 + b1 (+ dist*W1[256]) -> silu -> split -> A planes ----
    {
        const int r = tid >> 2, q4 = tid & 3;
        float dv = 0.0f;
        if (mode == 0) {
            long long e = (long long)tile * TMR + r;
            dv = (e < EE) ? g_dist[e] : 0.0f;
        }
        __nv_bfloat16* dh = sAhi + r * LDA + q4 * 32;
        __nv_bfloat16* dm = sAmid + r * LDA + q4 * 32;
        const float* st = stage + r * LDA + q4 * 32;
#pragma unroll
        for (int i = 0; i < 32; i++) {
            const int cc = q4 * 32 + i;
            float v = st[i] + B1[cc];
            if (mode == 0) v += dv * W1f[(size_t)256 * 128 + cc];
            v = silu_f(v);
            split_bf16(v, dh[i], dm[i]);
        }
    }
    __syncthreads();   // stage fully read before W2 overwrites it

    // ---- load W2 -> B planes ----
    {
        const int k = tid >> 1, half = tid & 1;
        const uint4* shi = (const uint4*)(w2hi + (size_t)k * HH + half * 64);
        const uint4* smi = (const uint4*)(w2mid + (size_t)k * HH + half * 64);
        uint4* dh = (uint4*)(sBhi + k * LDA + half * 64);
        uint4* dm = (uint4*)(sBmid + k * LDA + half * 64);
#pragma unroll
        for (int i = 0; i < 8; i++) { dh[i] = shi[i]; dm[i] = smi[i]; }
    }
    __syncthreads();

    // ================= GEMM2: K = 128 =================
#pragma unroll
    for (int mt = 0; mt < 2; mt++)
#pragma unroll
        for (int nt = 0; nt < 2; nt++)
            wmma::fill_fragment(acc[mt][nt], 0.0f);

    for (int ks = 0; ks < 8; ks++) {
        const int k0 = ks * 16;
        wmma::fragment<wmma::matrix_b, 16, 16, 16, __nv_bfloat16, wmma::row_major> bh[2], bm[2];
#pragma unroll
        for (int nt = 0; nt < 2; nt++) {
            wmma::load_matrix_sync(bh[nt], sBhi + k0 * LDA + wc * 32 + nt * 16, LDA);
            wmma::load_matrix_sync(bm[nt], sBmid + k0 * LDA + wc * 32 + nt * 16, LDA);
        }
#pragma unroll
        for (int mt = 0; mt < 2; mt++) {
            const int r0 = wr * 32 + mt * 16;
            wmma::fragment<wmma::matrix_a, 16, 16, 16, __nv_bfloat16, wmma::row_major> ah, am;
            wmma::load_matrix_sync(ah, sAhi + r0 * LDA + k0, LDA);
            wmma::load_matrix_sync(am, sAmid + r0 * LDA + k0, LDA);
#pragma unroll
            for (int nt = 0; nt < 2; nt++) {
                wmma::mma_sync(acc[mt][nt], ah, bh[nt], acc[mt][nt]);
                wmma::mma_sync(acc[mt][nt], ah, bm[nt], acc[mt][nt]);
                wmma::mma_sync(acc[mt][nt], am, bh[nt], acc[mt][nt]);
            }
        }
    }
    __syncthreads();   // GEMM2 reads of B planes done

    // ---- store acc2 -> stage ----
#pragma unroll
    for (int mt = 0; mt < 2; mt++)
#pragma unroll
        for (int nt = 0; nt < 2; nt++)
            wmma::store_matrix_sync(stage + (wr * 32 + mt * 16) * LDA + wc * 32 + nt * 16,
                                    acc[mt][nt], LDA, wmma::mem_row_major);
    __syncthreads();

    // ---- epilogue 2: + b2, output ----
    if (mode == 0) {
        // coalesced store of messages (no atomics)
        for (int rr = wid; rr < TMR; rr += 8) {
            long long e = (long long)tile * TMR + rr;
            if (e < EE) {
                const float4 v = *(const float4*)(stage + rr * LDA + lane * 4);
                const float4 b = *(const float4*)(B2 + lane * 4);
                *(float4*)(g_msg + (size_t)e * HH + lane * 4) =
                    make_float4(v.x + b.x, v.y + b.y, v.z + b.z, v.w + b.w);
            }
        }
    } else {
        for (int rr = wid; rr < TMR; rr += 8) {
            int n = tile * TMR + rr;
            if (n < NN) {
                const float4 v = *(const float4*)(stage + rr * LDA + lane * 4);
                const float4 b = *(const float4*)(B2 + lane * 4);
                float4 o = make_float4(v.x + b.x, v.y + b.y, v.z + b.z, v.w + b.w);
                *(float4*)(g_h + (size_t)n * HH + lane * 4) = o;
                __nv_bfloat16* dh = g_hhi + (size_t)n * HH + lane * 4;
                __nv_bfloat16* dm = g_hmid + (size_t)n * HH + lane * 4;
                __nv_bfloat16 h0, m0, h1, m1, h2, m2, h3, m3;
                split_bf16(o.x, h0, m0); split_bf16(o.y, h1, m1);
                split_bf16(o.z, h2, m2); split_bf16(o.w, h3, m3);
                dh[0] = h0; dh[1] = h1; dh[2] = h2; dh[3] = h3;
                dm[0] = m0; dm[1] = m1; dm[2] = m2; dm[3] = m3;
            }
        }
    }
}

// ---------------- pooling + output head ----------------
__global__ void pool_kernel(const void* batch) {
    int idx = blockIdx.x * blockDim.x + threadIdx.x;
    if (idx >= NN * 32) return;
    int n = idx >> 5, qq = idx & 31;
    int b = ld_idx(batch, n, g_is64);
    float4 v = ((const float4*)(g_h + (size_t)n * HH))[qq];
    float* dst = &g_pool[b * HH + qq * 4];
    atomicAdd(dst + 0, v.x);
    atomicAdd(dst + 1, v.y);
    atomicAdd(dst + 2, v.z);
    atomicAdd(dst + 3, v.w);
}

__global__ void out_kernel(const float* __restrict__ w1, const float* __restrict__ b1,
                           const float* __restrict__ w2, const float* __restrict__ b2,
                           float* __restrict__ out) {
    int gi = blockIdx.x;
    int j = threadIdx.x;  // 0..31
    float s = b1[j];
    for (int k = 0; k < HH; k++)
        s += g_pool[gi * HH + k] * w1[k * 32 + j];
    float v = silu_f(s) * w2[j];
#pragma unroll
    for (int o = 16; o > 0; o >>= 1)
        v += __shfl_down_sync(0xFFFFFFFFu, v, o);
    if (j == 0) out[gi] = v + b2[0];
}

extern "C" void kernel_launch(void* const* d_in, const int* in_sizes, int n_in,
                              void* d_out, int out_size) {
    const float* x       = (const float*)d_in[0];
    const float* pos     = (const float*)d_in[1];
    const void*  ei      = d_in[2];
    const void*  batch   = d_in[3];
    const float* emb_w   = (const float*)d_in[4];
    const float* emb_b   = (const float*)d_in[5];
    const float* msg_w1  = (const float*)d_in[6];
    const float* msg_b1  = (const float*)d_in[7];
    const float* msg_w2  = (const float*)d_in[8];
    const float* msg_b2  = (const float*)d_in[9];
    const float* node_w1 = (const float*)d_in[10];
    const float* node_b1 = (const float*)d_in[11];
    const float* node_w2 = (const float*)d_in[12];
    const float* node_b2 = (const float*)d_in[13];
    const float* out_w1  = (const float*)d_in[14];
    const float* out_b1  = (const float*)d_in[15];
    const float* out_w2  = (const float*)d_in[16];
    const float* out_b2  = (const float*)d_in[17];

    cudaFuncSetAttribute(layer_kernel, cudaFuncAttributeMaxDynamicSharedMemorySize,
                         SMEM_LAYER);

    detect_kernel<<<1, 256>>>((const int*)ei);
    prep_w_kernel<<<(LL * WROWS * HH + 255) / 256, 256>>>(msg_w1, msg_w2, node_w1, node_w2);
    embed_kernel<<<(NN * HH + 255) / 256, 256>>>(x, emb_w, emb_b);
    dist_kernel<<<(EE + 255) / 256, 256>>>(pos, ei);

    // CSR build (graph fixed for the whole launch)
    zero_cnt_kernel<<<(NN + 255) / 256, 256>>>();
    hist_kernel<<<(EE + 255) / 256, 256>>>(ei);
    scan_kernel<<<1, 1024>>>();
    fill_kernel<<<(EE + 255) / 256, 256>>>(ei);

    const int egrid = EE / TMR;               // 9375 (exact)
    const int ngrid = (NN + TMR - 1) / TMR;   // 469
    const int agrid = (NN + 7) / 8;           // warp per node

    for (int l = 0; l < LL; l++) {
        layer_kernel<<<egrid, 256, SMEM_LAYER>>>(
            0, l, ei,
            msg_w1 + (size_t)l * 257 * HH,
            msg_b1 + (size_t)l * HH, msg_b2 + (size_t)l * HH);
        aggregate_kernel<<<agrid, 256>>>();
        layer_kernel<<<ngrid, 256, SMEM_LAYER>>>(
            1, l, ei,
            nullptr,
            node_b1 + (size_t)l * HH, node_b2 + (size_t)l * HH);
    }

    zero_pool_kernel<<<(GG * HH + 255) / 256, 256>>>();
    pool_kernel<<<(NN * 32 + 255) / 256, 256>>>(batch);
    out_kernel<<<GG, 32>>>(out_w1, out_b1, out_w2, out_b2, (float*)d_out);
}

// round 16
// speedup vs baseline: 1.0564x; 1.0564x over previous
#include <cuda_runtime.h>
#include <cuda_bf16.h>
#include <mma.h>
#include <cstdint>

using namespace nvcuda;

#define NN 30000
#define EE 600000
#define HH 128
#define LL 4
#define GG 64
#define TMR 128      // rows per tile (round-11 validated geometry)
#define LDA 136      // leading dim (elements) for bf16 planes and float stage
#define WROWS 769    // per-layer pre-split weight rows: 257 + 128 + 256 + 128

// ---------------- scratch (static device globals; no allocation) ----------
__device__ __align__(256) float g_h[NN * HH];        // fp32 h (for pool)
__device__ __align__(256) __nv_bfloat16 g_hhi[NN * HH];
__device__ __align__(256) __nv_bfloat16 g_hmid[NN * HH];
__device__ __align__(256) float g_aggr[NN * HH];
__device__ __align__(256) float g_msg[(size_t)EE * HH];   // messages in SORTED order
__device__ __align__(256) float g_dist[EE];
__device__ __align__(256) float g_pool[GG * HH];
__device__ __align__(256) __nv_bfloat16 g_whi[LL * WROWS * HH];
__device__ __align__(256) __nv_bfloat16 g_wmid[LL * WROWS * HH];
__device__ int g_cnt[NN];
__device__ int g_off[NN + 1];
__device__ int g_cursor[NN];
__device__ int g_perm[EE];     // sorted position -> physical edge id
__device__ int g_is64;

// ---------------- helpers ----------------
__device__ __forceinline__ int ld_idx(const void* p, long long i, int is64) {
    if (is64) return (int)((const long long*)p)[i];
    return ((const int*)p)[i];
}
__device__ __forceinline__ float silu_f(float v) {
    return v / (1.0f + __expf(-v));
}
__device__ __forceinline__ void split_bf16(float x, __nv_bfloat16& h, __nv_bfloat16& m) {
    h = __float2bfloat16_rn(x);
    float r = x - __bfloat162float(h);
    m = __float2bfloat16_rn(r);
}

// ---------------- auxiliary kernels ----------------
__global__ void detect_kernel(const int* w) {
    __shared__ int nz;
    if (threadIdx.x == 0) nz = 0;
    __syncthreads();
    int f = 0;
    for (int i = threadIdx.x * 2 + 1; i < 4096; i += 2 * 256)
        if (w[i] != 0) f = 1;
    if (f) atomicOr(&nz, 1);
    __syncthreads();
    if (threadIdx.x == 0) g_is64 = (nz == 0) ? 1 : 0;
}

__global__ void prep_w_kernel(const float* __restrict__ msg_w1,
                              const float* __restrict__ msg_w2,
                              const float* __restrict__ node_w1,
                              const float* __restrict__ node_w2) {
    int id = blockIdx.x * blockDim.x + threadIdx.x;
    if (id >= LL * WROWS * HH) return;
    int l = id / (WROWS * HH);
    int rem = id - l * (WROWS * HH);
    int row = rem >> 7, n = rem & 127;
    float v;
    if (row < 257)      v = msg_w1[((size_t)l * 257 + row) * HH + n];
    else if (row < 385) v = msg_w2[((size_t)l * 128 + (row - 257)) * HH + n];
    else if (row < 641) v = node_w1[((size_t)l * 256 + (row - 385)) * HH + n];
    else                v = node_w2[((size_t)l * 128 + (row - 641)) * HH + n];
    __nv_bfloat16 h, m;
    split_bf16(v, h, m);
    g_whi[id] = h;
    g_wmid[id] = m;
}

__global__ void embed_kernel(const float* __restrict__ x,
                             const float* __restrict__ w,
                             const float* __restrict__ b) {
    int idx = blockIdx.x * blockDim.x + threadIdx.x;
    if (idx >= NN * HH) return;
    int n = idx >> 7, k = idx & 127;
    float v = x[n] * w[k] + b[k];
    g_h[idx] = v;
    __nv_bfloat16 h, m;
    split_bf16(v, h, m);
    g_hhi[idx] = h;
    g_hmid[idx] = m;
}

__global__ void dist_kernel(const float* __restrict__ pos, const void* ei) {
    int e = blockIdx.x * blockDim.x + threadIdx.x;
    if (e >= EE) return;
    int is64 = g_is64;
    int r = ld_idx(ei, e, is64);
    int c = ld_idx(ei, (long long)EE + e, is64);
    float dx = pos[3 * r + 0] - pos[3 * c + 0];
    float dy = pos[3 * r + 1] - pos[3 * c + 1];
    float dz = pos[3 * r + 2] - pos[3 * c + 2];
    g_dist[e] = dx * dx + dy * dy + dz * dz;
}

// ---------------- CSR build (once per launch) ----------------
__global__ void zero_cnt_kernel() {
    int i = blockIdx.x * blockDim.x + threadIdx.x;
    if (i < NN) g_cnt[i] = 0;
}
__global__ void hist_kernel(const void* ei) {
    int e = blockIdx.x * blockDim.x + threadIdx.x;
    if (e >= EE) return;
    atomicAdd(&g_cnt[ld_idx(ei, (long long)EE + e, g_is64)], 1);
}
__global__ void scan_kernel() {
    __shared__ int ssum[1024];
    const int t = threadIdx.x;
    const int base = t * 30;   // 1024*30 = 30720 >= NN
    int s = 0;
    for (int i = 0; i < 30; i++) {
        int idx = base + i;
        if (idx < NN) s += g_cnt[idx];
    }
    ssum[t] = s;
    __syncthreads();
    for (int off = 1; off < 1024; off <<= 1) {
        int v = (t >= off) ? ssum[t - off] : 0;
        __syncthreads();
        ssum[t] += v;
        __syncthreads();
    }
    int run = (t == 0) ? 0 : ssum[t - 1];
    for (int i = 0; i < 30; i++) {
        int idx = base + i;
        if (idx < NN) {
            g_off[idx] = run;
            g_cursor[idx] = run;
            run += g_cnt[idx];
        }
    }
    if (t == 1023) g_off[NN] = run;
}
__global__ void fill_kernel(const void* ei) {
    int e = blockIdx.x * blockDim.x + threadIdx.x;
    if (e >= EE) return;
    int c = ld_idx(ei, (long long)EE + e, g_is64);
    int pos = atomicAdd(&g_cursor[c], 1);
    g_perm[pos] = e;
}

// ---------------- aggregate: warp per node, CONTIGUOUS message rows --------
__global__ __launch_bounds__(256) void aggregate_kernel() {
    const int wid = threadIdx.x >> 5, lane = threadIdx.x & 31;
    const int n = blockIdx.x * 8 + wid;
    if (n >= NN) return;
    const int start = g_off[n], end = g_off[n + 1];
    float4 a0 = make_float4(0.f, 0.f, 0.f, 0.f);
    float4 a1 = make_float4(0.f, 0.f, 0.f, 0.f);
    int i = start;
    for (; i + 1 < end; i += 2) {
        float4 v0 = *(const float4*)(g_msg + (size_t)i * HH + lane * 4);
        float4 v1 = *(const float4*)(g_msg + (size_t)(i + 1) * HH + lane * 4);
        a0.x += v0.x; a0.y += v0.y; a0.z += v0.z; a0.w += v0.w;
        a1.x += v1.x; a1.y += v1.y; a1.z += v1.z; a1.w += v1.w;
    }
    if (i < end) {
        float4 v0 = *(const float4*)(g_msg + (size_t)i * HH + lane * 4);
        a0.x += v0.x; a0.y += v0.y; a0.z += v0.z; a0.w += v0.w;
    }
    a0.x += a1.x; a0.y += a1.y; a0.z += a1.z; a0.w += a1.w;
    *(float4*)(g_aggr + (size_t)n * HH + lane * 4) = a0;
}

__global__ void zero_pool_kernel() {
    int idx = blockIdx.x * blockDim.x + threadIdx.x;
    if (idx < GG * HH) g_pool[idx] = 0.0f;
}

// ---------------------------------------------------------------------------
// Fused MLP layer kernel (WMMA bf16, 2-way split, 3-term). TMR=128.
// mode 0 = edge (rows = SORTED edges via g_perm), 1 = node.
// SMEM: sAhi|sAmid|sBhi|sBmid (each 128*136 bf16 = 34816B);
//       stage float[128][136] overlays sBhi..sBmid; sCol/sRow/sE at end.
// ---------------------------------------------------------------------------
#define SMEM_LAYER 140800

__global__ __launch_bounds__(256) void layer_kernel(
    int mode, int layer, const void* __restrict__ ei,
    const float* __restrict__ W1f,
    const float* __restrict__ B1, const float* __restrict__ B2) {
    extern __shared__ char smem[];
    __nv_bfloat16* sAhi  = (__nv_bfloat16*)smem;
    __nv_bfloat16* sAmid = sAhi + TMR * LDA;
    __nv_bfloat16* sBhi  = sAmid + TMR * LDA;
    __nv_bfloat16* sBmid = sBhi + TMR * LDA;
    float* stage = (float*)sBhi;                  // overlays both B planes
    int* sCol = (int*)(sBmid + TMR * LDA);
    int* sRow = sCol + TMR;
    int* sE   = sRow + TMR;                       // physical edge ids

    const size_t lbase = (size_t)layer * WROWS * HH;
    const __nv_bfloat16* w1hi  = g_whi  + lbase + (size_t)(mode == 0 ? 0 : 385) * HH;
    const __nv_bfloat16* w1mid = g_wmid + lbase + (size_t)(mode == 0 ? 0 : 385) * HH;
    const __nv_bfloat16* w2hi  = g_whi  + lbase + (size_t)(mode == 0 ? 257 : 641) * HH;
    const __nv_bfloat16* w2mid = g_wmid + lbase + (size_t)(mode == 0 ? 257 : 641) * HH;

    const int tid = threadIdx.x, lane = tid & 31, wid = tid >> 5;
    const int wr = wid & 1, wc = wid >> 1;        // warp tile: rows wr*64, cols wc*32
    const int tile = blockIdx.x;
    const int is64 = g_is64;

    if (tid < TMR) {
        if (mode == 0) {
            long long g = (long long)tile * TMR + tid;
            int e = g_perm[(g < EE) ? g : 0];
            sE[tid] = e;
            sRow[tid] = ld_idx(ei, e, is64);
            sCol[tid] = ld_idx(ei, (long long)EE + e, is64);
        } else {
            int n = tile * TMR + tid;
            sCol[tid] = (n < NN) ? n : 0;
        }
    }
    __syncthreads();

    wmma::fragment<wmma::accumulator, 16, 16, 16, float> acc[4][2];
#pragma unroll
    for (int mt = 0; mt < 4; mt++)
#pragma unroll
        for (int nt = 0; nt < 2; nt++)
            wmma::fill_fragment(acc[mt][nt], 0.0f);

    // ================= GEMM1: K chunks of 128 =================
    for (int c = 0; c < 2; c++) {
        if (c) __syncthreads();   // previous chunk reads complete before refill

        // ---- A chunk ----
        const int r = tid >> 1, half = tid & 1;
        if (mode == 0 || c == 0) {
            const int node = (mode == 0) ? ((c == 0) ? sCol[r] : sRow[r]) : sCol[r];
            const uint4* shi = (const uint4*)(g_hhi + (size_t)node * HH + half * 64);
            const uint4* smi = (const uint4*)(g_hmid + (size_t)node * HH + half * 64);
            uint4* dh = (uint4*)(sAhi + r * LDA + half * 64);
            uint4* dm = (uint4*)(sAmid + r * LDA + half * 64);
#pragma unroll
            for (int i = 0; i < 8; i++) { dh[i] = shi[i]; dm[i] = smi[i]; }
        } else {
            const float4* s4 = (const float4*)(g_aggr + (size_t)sCol[r] * HH + half * 64);
            __nv_bfloat16* dh = sAhi + r * LDA + half * 64;
            __nv_bfloat16* dm = sAmid + r * LDA + half * 64;
#pragma unroll
            for (int i = 0; i < 16; i++) {
                float4 v = s4[i];
                split_bf16(v.x, dh[i * 4 + 0], dm[i * 4 + 0]);
                split_bf16(v.y, dh[i * 4 + 1], dm[i * 4 + 1]);
                split_bf16(v.z, dh[i * 4 + 2], dm[i * 4 + 2]);
                split_bf16(v.w, dh[i * 4 + 3], dm[i * 4 + 3]);
            }
        }
        // ---- B chunk: pure copy of pre-split weights ----
        {
            const int k = tid >> 1;
            const uint4* shi = (const uint4*)(w1hi + (size_t)(c * 128 + k) * HH + half * 64);
            const uint4* smi = (const uint4*)(w1mid + (size_t)(c * 128 + k) * HH + half * 64);
            uint4* dh = (uint4*)(sBhi + k * LDA + half * 64);
            uint4* dm = (uint4*)(sBmid + k * LDA + half * 64);
#pragma unroll
            for (int i = 0; i < 8; i++) { dh[i] = shi[i]; dm[i] = smi[i]; }
        }
        __syncthreads();

        for (int ks = 0; ks < 8; ks++) {
            const int k0 = ks * 16;
            wmma::fragment<wmma::matrix_b, 16, 16, 16, __nv_bfloat16, wmma::row_major> bh[2], bm[2];
#pragma unroll
            for (int nt = 0; nt < 2; nt++) {
                wmma::load_matrix_sync(bh[nt], sBhi + k0 * LDA + wc * 32 + nt * 16, LDA);
                wmma::load_matrix_sync(bm[nt], sBmid + k0 * LDA + wc * 32 + nt * 16, LDA);
            }
#pragma unroll
            for (int mt = 0; mt < 4; mt++) {
                const int r0 = wr * 64 + mt * 16;
                wmma::fragment<wmma::matrix_a, 16, 16, 16, __nv_bfloat16, wmma::row_major> ah, am;
                wmma::load_matrix_sync(ah, sAhi + r0 * LDA + k0, LDA);
                wmma::load_matrix_sync(am, sAmid + r0 * LDA + k0, LDA);
#pragma unroll
                for (int nt = 0; nt < 2; nt++) {
                    wmma::mma_sync(acc[mt][nt], ah, bh[nt], acc[mt][nt]);
                    wmma::mma_sync(acc[mt][nt], ah, bm[nt], acc[mt][nt]);
                    wmma::mma_sync(acc[mt][nt], am, bh[nt], acc[mt][nt]);
                }
            }
        }
    }
    __syncthreads();   // all GEMM1 reads of B planes done; stage may be written

    // ---- store acc1 -> stage (fp32) ----
#pragma unroll
    for (int mt = 0; mt < 4; mt++)
#pragma unroll
        for (int nt = 0; nt < 2; nt++)
            wmma::store_matrix_sync(stage + (wr * 64 + mt * 16) * LDA + wc * 32 + nt * 16,
                                    acc[mt][nt], LDA, wmma::mem_row_major);
    __syncthreads();

    // ---- epilogue 1: D1 + b1 (+ dist*W1[256]) -> silu -> split -> A planes ----
    {
        const int r = tid >> 1, half = tid & 1;
        float dv = 0.0f;
        if (mode == 0) {
            long long g = (long long)tile * TMR + r;
            dv = (g < EE) ? g_dist[sE[r]] : 0.0f;
        }
        __nv_bfloat16* dh = sAhi + r * LDA + half * 64;
        __nv_bfloat16* dm = sAmid + r * LDA + half * 64;
        const float* st = stage + r * LDA + half * 64;
#pragma unroll
        for (int i = 0; i < 64; i++) {
            const int cc = half * 64 + i;
            float v = st[i] + B1[cc];
            if (mode == 0) v += dv * W1f[(size_t)256 * 128 + cc];
            v = silu_f(v);
            split_bf16(v, dh[i], dm[i]);
        }
    }
    __syncthreads();   // stage fully read before W2 overwrites it

    // ---- load W2 -> B planes (pure copy) ----
    {
        const int k = tid >> 1, half = tid & 1;
        const uint4* shi = (const uint4*)(w2hi + (size_t)k * HH + half * 64);
        const uint4* smi = (const uint4*)(w2mid + (size_t)k * HH + half * 64);
        uint4* dh = (uint4*)(sBhi + k * LDA + half * 64);
        uint4* dm = (uint4*)(sBmid + k * LDA + half * 64);
#pragma unroll
        for (int i = 0; i < 8; i++) { dh[i] = shi[i]; dm[i] = smi[i]; }
    }
    __syncthreads();

    // ================= GEMM2: K = 128 =================
#pragma unroll
    for (int mt = 0; mt < 4; mt++)
#pragma unroll
        for (int nt = 0; nt < 2; nt++)
            wmma::fill_fragment(acc[mt][nt], 0.0f);

    for (int ks = 0; ks < 8; ks++) {
        const int k0 = ks * 16;
        wmma::fragment<wmma::matrix_b, 16, 16, 16, __nv_bfloat16, wmma::row_major> bh[2], bm[2];
#pragma unroll
        for (int nt = 0; nt < 2; nt++) {
            wmma::load_matrix_sync(bh[nt], sBhi + k0 * LDA + wc * 32 + nt * 16, LDA);
            wmma::load_matrix_sync(bm[nt], sBmid + k0 * LDA + wc * 32 + nt * 16, LDA);
        }
#pragma unroll
        for (int mt = 0; mt < 4; mt++) {
            const int r0 = wr * 64 + mt * 16;
            wmma::fragment<wmma::matrix_a, 16, 16, 16, __nv_bfloat16, wmma::row_major> ah, am;
            wmma::load_matrix_sync(ah, sAhi + r0 * LDA + k0, LDA);
            wmma::load_matrix_sync(am, sAmid + r0 * LDA + k0, LDA);
#pragma unroll
            for (int nt = 0; nt < 2; nt++) {
                wmma::mma_sync(acc[mt][nt], ah, bh[nt], acc[mt][nt]);
                wmma::mma_sync(acc[mt][nt], ah, bm[nt], acc[mt][nt]);
                wmma::mma_sync(acc[mt][nt], am, bh[nt], acc[mt][nt]);
            }
        }
    }
    __syncthreads();   // all GEMM2 reads of B planes done

    // ---- store acc2 -> stage ----
#pragma unroll
    for (int mt = 0; mt < 4; mt++)
#pragma unroll
        for (int nt = 0; nt < 2; nt++)
            wmma::store_matrix_sync(stage + (wr * 64 + mt * 16) * LDA + wc * 32 + nt * 16,
                                    acc[mt][nt], LDA, wmma::mem_row_major);
    __syncthreads();

    // ---- epilogue 2: + b2, output ----
    if (mode == 0) {
        // coalesced store of messages at SORTED slots (no atomics)
        for (int rr = wid; rr < TMR; rr += 8) {
            long long g = (long long)tile * TMR + rr;
            if (g < EE) {
                const float4 v = *(const float4*)(stage + rr * LDA + lane * 4);
                const float4 b = *(const float4*)(B2 + lane * 4);
                *(float4*)(g_msg + (size_t)g * HH + lane * 4) =
                    make_float4(v.x + b.x, v.y + b.y, v.z + b.z, v.w + b.w);
            }
        }
    } else {
        for (int rr = wid; rr < TMR; rr += 8) {
            int n = tile * TMR + rr;
            if (n < NN) {
                const float4 v = *(const float4*)(stage + rr * LDA + lane * 4);
                const float4 b = *(const float4*)(B2 + lane * 4);
                float4 o = make_float4(v.x + b.x, v.y + b.y, v.z + b.z, v.w + b.w);
                *(float4*)(g_h + (size_t)n * HH + lane * 4) = o;
                __nv_bfloat16* dh = g_hhi + (size_t)n * HH + lane * 4;
                __nv_bfloat16* dm = g_hmid + (size_t)n * HH + lane * 4;
                __nv_bfloat16 h0, m0, h1, m1, h2, m2, h3, m3;
                split_bf16(o.x, h0, m0); split_bf16(o.y, h1, m1);
                split_bf16(o.z, h2, m2); split_bf16(o.w, h3, m3);
                dh[0] = h0; dh[1] = h1; dh[2] = h2; dh[3] = h3;
                dm[0] = m0; dm[1] = m1; dm[2] = m2; dm[3] = m3;
            }
        }
    }
}

// ---------------- pooling + output head ----------------
__global__ void pool_kernel(const void* batch) {
    int idx = blockIdx.x * blockDim.x + threadIdx.x;
    if (idx >= NN * 32) return;
    int n = idx >> 5, qq = idx & 31;
    int b = ld_idx(batch, n, g_is64);
    float4 v = ((const float4*)(g_h + (size_t)n * HH))[qq];
    float* dst = &g_pool[b * HH + qq * 4];
    atomicAdd(dst + 0, v.x);
    atomicAdd(dst + 1, v.y);
    atomicAdd(dst + 2, v.z);
    atomicAdd(dst + 3, v.w);
}

__global__ void out_kernel(const float* __restrict__ w1, const float* __restrict__ b1,
                           const float* __restrict__ w2, const float* __restrict__ b2,
                           float* __restrict__ out) {
    int gi = blockIdx.x;
    int j = threadIdx.x;  // 0..31
    float s = b1[j];
    for (int k = 0; k < HH; k++)
        s += g_pool[gi * HH + k] * w1[k * 32 + j];
    float v = silu_f(s) * w2[j];
#pragma unroll
    for (int o = 16; o > 0; o >>= 1)
        v += __shfl_down_sync(0xFFFFFFFFu, v, o);
    if (j == 0) out[gi] = v + b2[0];
}

extern "C" void kernel_launch(void* const* d_in, const int* in_sizes, int n_in,
                              void* d_out, int out_size) {
    const float* x       = (const float*)d_in[0];
    const float* pos     = (const float*)d_in[1];
    const void*  ei      = d_in[2];
    const void*  batch   = d_in[3];
    const float* emb_w   = (const float*)d_in[4];
    const float* emb_b   = (const float*)d_in[5];
    const float* msg_w1  = (const float*)d_in[6];
    const float* msg_b1  = (const float*)d_in[7];
    const float* msg_w2  = (const float*)d_in[8];
    const float* msg_b2  = (const float*)d_in[9];
    const float* node_w1 = (const float*)d_in[10];
    const float* node_b1 = (const float*)d_in[11];
    const float* node_w2 = (const float*)d_in[12];
    const float* node_b2 = (const float*)d_in[13];
    const float* out_w1  = (const float*)d_in[14];
    const float* out_b1  = (const float*)d_in[15];
    const float* out_w2  = (const float*)d_in[16];
    const float* out_b2  = (const float*)d_in[17];

    cudaFuncSetAttribute(layer_kernel, cudaFuncAttributeMaxDynamicSharedMemorySize,
                         SMEM_LAYER);

    detect_kernel<<<1, 256>>>((const int*)ei);
    prep_w_kernel<<<(LL * WROWS * HH + 255) / 256, 256>>>(msg_w1, msg_w2, node_w1, node_w2);
    embed_kernel<<<(NN * HH + 255) / 256, 256>>>(x, emb_w, emb_b);
    dist_kernel<<<(EE + 255) / 256, 256>>>(pos, ei);

    // CSR build (graph fixed for the whole launch)
    zero_cnt_kernel<<<(NN + 255) / 256, 256>>>();
    hist_kernel<<<(EE + 255) / 256, 256>>>(ei);
    scan_kernel<<<1, 1024>>>();
    fill_kernel<<<(EE + 255) / 256, 256>>>(ei);

    const int egrid = (EE + TMR - 1) / TMR;   // 4688
    const int ngrid = (NN + TMR - 1) / TMR;   // 235
    const int agrid = (NN + 7) / 8;           // warp per node

    for (int l = 0; l < LL; l++) {
        layer_kernel<<<egrid, 256, SMEM_LAYER>>>(
            0, l, ei,
            msg_w1 + (size_t)l * 257 * HH,
            msg_b1 + (size_t)l * HH, msg_b2 + (size_t)l * HH);
        aggregate_kernel<<<agrid, 256>>>();
        layer_kernel<<<ngrid, 256, SMEM_LAYER>>>(
            1, l, ei,
            nullptr,
            node_b1 + (size_t)l * HH, node_b2 + (size_t)l * HH);
    }

    zero_pool_kernel<<<(GG * HH + 255) / 256, 256>>>();
    pool_kernel<<<(NN * 32 + 255) / 256, 256>>>(batch);
    out_kernel<<<GG, 32>>>(out_w1, out_b1, out_w2, out_b2, (float*)d_out);
}